// round 9
// baseline (speedup 1.0000x reference)
#include <cuda_runtime.h>
#include <cuda_fp16.h>
#include <cstdint>

// ---------------- problem constants ----------------
#define B_    32
#define DD    512
#define KK    64
#define KTOT  32768            // K*D : flattened reduction dim
#define MM    2048             // B*F_out
#define SPLIT 16
#define KPER  (KTOT / SPLIT)   // 2048
#define BK    64               // k elems per pipeline stage (128 B rows)
#define NCH   (KPER / BK)      // 32
#define BM    64
#define BN    128
#define NSTG  3
#define STAGE_BYTES 24576      // A 8K + B 16K
#define GEMM_SMEM   (NSTG * STAGE_BYTES + 1024)
#define S1_SMEM     131072     // sX 64K + sC 64K

// ---------------- device scratch (no allocation) ----------------
__device__ __half g_A[(size_t)MM * KTOT];          // 128 MB (fp16 T)
__device__ __half g_B[(size_t)DD * KTOT];          // 32 MB  (W^T fp16)
__device__ __half g_C[(size_t)KK * 64 * 64];       // 512 KB (coeff [k][o][i] fp16)
__device__ float  g_part[(size_t)SPLIT * MM * DD]; // 64 MB

// ---------------- helpers ----------------
__device__ __forceinline__ uint32_t smem_u32(const void* p) {
    uint32_t a;
    asm("{ .reg .u64 t; cvta.to.shared.u64 t, %1; cvt.u32.u64 %0, t; }" : "=r"(a) : "l"(p));
    return a;
}
__device__ __forceinline__ void cp16(uint32_t dst, const void* src) {
    asm volatile("cp.async.cg.shared.global [%0], [%1], 16;" :: "r"(dst), "l"(src));
}
#define CP_COMMIT() asm volatile("cp.async.commit_group;" ::: "memory")
#define CP_WAIT(n)  asm volatile("cp.async.wait_group %0;" :: "n"(n) : "memory")

__device__ __forceinline__ void ldsm4(uint32_t* r, uint32_t addr) {
    asm volatile("ldmatrix.sync.aligned.m8n8.x4.shared.b16 {%0,%1,%2,%3}, [%4];"
                 : "=r"(r[0]), "=r"(r[1]), "=r"(r[2]), "=r"(r[3]) : "r"(addr));
}
__device__ __forceinline__ void mma_f16(float* c, const uint32_t* a, const uint32_t* b) {
    asm volatile(
        "mma.sync.aligned.m16n8k16.row.col.f32.f16.f16.f32 "
        "{%0,%1,%2,%3},{%4,%5,%6,%7},{%8,%9},{%0,%1,%2,%3};"
        : "+f"(c[0]), "+f"(c[1]), "+f"(c[2]), "+f"(c[3])
        : "r"(a[0]), "r"(a[1]), "r"(a[2]), "r"(a[3]), "r"(b[0]), "r"(b[1]));
}

// ---------------------------------------------------------------------------
// coeff transpose: coeff[o,i,k] f32 -> g_C[k][o][i] f16
// ---------------------------------------------------------------------------
__global__ void __launch_bounds__(256) ctrans_kernel(const float* __restrict__ coeff) {
    const int k = blockIdx.x;
    for (int idx = threadIdx.x; idx < 4096; idx += 256)
        g_C[k * 4096 + idx] = __float2half_rn(coeff[(size_t)idx * 64 + k]);
}

// ---------------------------------------------------------------------------
// W transpose + fp16: W[(k,e)][d] f32 -> g_B[d][(k,e)] f16
// ---------------------------------------------------------------------------
__global__ void __launch_bounds__(256) wsplit_kernel(const float* __restrict__ W) {
    __shared__ float s[32][33];
    const int kb = blockIdx.x;
    const int nb = blockIdx.y;
    const int tx = threadIdx.x & 31, tg = threadIdx.x >> 5;

#pragma unroll
    for (int r = 0; r < 4; ++r) {
        int kr = tg + r * 8;
        s[kr][tx] = W[(size_t)(kb * 32 + kr) * DD + nb * 32 + tx];
    }
    __syncthreads();
#pragma unroll
    for (int r = 0; r < 4; ++r) {
        int nr = tg + r * 8;
        g_B[(size_t)(nb * 32 + nr) * KTOT + kb * 32 + tx] = __float2half_rn(s[tx][nr]);
    }
}

// ---------------------------------------------------------------------------
// Stage 1 (tensorized): T[b*64+o][k*512+e] = sum_i coeff[o,i,k]*x[b,i,e] -> f16
// ---------------------------------------------------------------------------
__global__ void __launch_bounds__(256, 1) stage1_mma_kernel(const float* __restrict__ x) {
    extern __shared__ char smem[];
    const uint32_t sb  = smem_u32(smem);
    const uint32_t sxb = sb;
    const uint32_t scb = sb + 65536;
    const int tid = threadIdx.x, lane = tid & 31, wid = tid >> 5;
    const int k = blockIdx.x * 8 + wid;
    const int b = blockIdx.y;

    const float* xb = x + (size_t)b * 64 * 512;
#pragma unroll 4
    for (int n = 0; n < 32; ++n) {
        int g = n * 256 + tid;
        int i = g >> 7, e = (g & 127) * 4;
        float4 v = *(const float4*)&xb[i * 512 + e];
        __half h[4] = {__float2half_rn(v.x), __float2half_rn(v.y),
                       __float2half_rn(v.z), __float2half_rn(v.w)};
#pragma unroll
        for (int j = 0; j < 4; ++j) {
            uint32_t off = (e + j) * 128 + ((i * 2) ^ (((e + j) & 7) * 16));
            *(__half*)(smem + off) = h[j];
        }
    }
    {
        const __half* gc = g_C + (size_t)k * 4096;
#pragma unroll
        for (int n = 0; n < 16; ++n) {
            int idx = n * 32 + lane;
            int o = idx >> 3, c8 = idx & 7;
            uint32_t off = 65536 + wid * 8192 + o * 128 + ((c8 * 16) ^ ((o & 7) * 16));
            *(int4*)(smem + off) = *(const int4*)(gc + o * 64 + c8 * 8);
        }
    }
    __syncthreads();

    const int a_row  = (lane & 7) | (((lane >> 3) & 1) << 3);
    const int a_k16b = (lane >> 4) * 16;
    const int b_nr   = (lane & 7) | (((lane >> 4) & 1) << 3);
    const int b_k16b = ((lane >> 3) & 1) * 16;

    uint32_t a[4][4][4];
#pragma unroll
    for (int ot = 0; ot < 4; ++ot)
#pragma unroll
        for (int k16 = 0; k16 < 4; ++k16) {
            int r = ot * 16 + a_row;
            uint32_t off = scb + wid * 8192 + r * 128 + ((k16 * 32 + a_k16b) ^ ((r & 7) * 16));
            ldsm4(a[ot][k16], off);
        }

    __half* gOut = g_A + (size_t)(b * 64) * KTOT + (size_t)k * 512;

#pragma unroll 1
    for (int et = 0; et < 16; ++et) {
        float acc[4][4][4];
#pragma unroll
        for (int ot = 0; ot < 4; ++ot)
#pragma unroll
            for (int nt = 0; nt < 4; ++nt)
#pragma unroll
                for (int j = 0; j < 4; ++j) acc[ot][nt][j] = 0.0f;

#pragma unroll
        for (int k16 = 0; k16 < 4; ++k16) {
            uint32_t bb[2][4];
#pragma unroll
            for (int p = 0; p < 2; ++p) {
                int nrow = et * 32 + p * 16 + b_nr;
                uint32_t off = sxb + nrow * 128 + ((k16 * 32 + b_k16b) ^ ((nrow & 7) * 16));
                ldsm4(bb[p], off);
            }
#pragma unroll
            for (int ot = 0; ot < 4; ++ot)
#pragma unroll
                for (int nt = 0; nt < 4; ++nt)
                    mma_f16(acc[ot][nt], a[ot][k16], &bb[nt >> 1][(nt & 1) * 2]);
        }
#pragma unroll
        for (int ot = 0; ot < 4; ++ot)
#pragma unroll
            for (int nt = 0; nt < 4; ++nt) {
                int o = ot * 16 + (lane >> 2);
                int e = et * 32 + nt * 8 + (lane & 3) * 2;
                *(__half2*)&gOut[(size_t)o * KTOT + e] =
                    __floats2half2_rn(acc[ot][nt][0], acc[ot][nt][1]);
                *(__half2*)&gOut[(size_t)(o + 8) * KTOT + e] =
                    __floats2half2_rn(acc[ot][nt][2], acc[ot][nt][3]);
            }
    }
}

// ---------------------------------------------------------------------------
// Stage 2: fp16 split-K GEMM, max-occupancy:
//  CTA 64x128, 8 warps, warp tile 32x32, NSTG=3 x 24KB, <=84 regs
//  -> 3 CTAs/SM = 24 warps/SM. grid (4, 32, 16) = 2048 CTAs (fine-grain pack).
// ---------------------------------------------------------------------------
__global__ void __launch_bounds__(256, 3) gemm_kernel() {
    extern __shared__ char smem[];
    const uint32_t sb = (smem_u32(smem) + 1023) & ~1023u;

    const int tid  = threadIdx.x;
    const int lane = tid & 31;
    const int wid  = tid >> 5;
    const int n0 = blockIdx.x * BN;
    const int m0 = blockIdx.y * BM;
    const size_t k0 = (size_t)blockIdx.z * KPER;
    const int warp_m = (wid & 1) * 32;
    const int warp_n = (wid >> 1) * 32;

    // ---- cp.async: A 64x128B, B 128x128B per stage ----
    const int rA = tid >> 2, cA = (tid & 3) * 2;      // A: 4 thr/row, 2 int4 each
    const int rB = tid >> 1, cB = (tid & 1) * 4;      // B: 2 thr/row, 4 int4 each
    const __half* gA = g_A + (size_t)(m0 + rA) * KTOT + k0 + cA * 8;
    const __half* gB = g_B + (size_t)(n0 + rB) * KTOT + k0 + cB * 8;

    uint32_t swzA[2], swzB[4];
#pragma unroll
    for (int j = 0; j < 2; ++j)
        swzA[j] = rA * 128 + (((cA + j) * 16) ^ ((rA & 7) * 16));
#pragma unroll
    for (int j = 0; j < 4; ++j)
        swzB[j] = 8192 + rB * 128 + (((cB + j) * 16) ^ ((rB & 7) * 16));

    const int a_row  = (lane & 7) | (((lane >> 3) & 1) << 3);
    const int a_k16b = (lane >> 4) * 16;
    const int b_nr   = (lane & 7) | (((lane >> 4) & 1) << 3);
    const int b_k16b = ((lane >> 3) & 1) * 16;

    float acc[2][4][4];
#pragma unroll
    for (int mt = 0; mt < 2; ++mt)
#pragma unroll
        for (int nt = 0; nt < 4; ++nt)
#pragma unroll
            for (int j = 0; j < 4; ++j) acc[mt][nt][j] = 0.0f;

    auto load_stage = [&](int c, int s) {
        const uint32_t base = sb + s * STAGE_BYTES;
        const int ke = c * BK;
#pragma unroll
        for (int j = 0; j < 2; ++j)
            cp16(base + swzA[j], gA + ke + j * 8);
#pragma unroll
        for (int j = 0; j < 4; ++j)
            cp16(base + swzB[j], gB + ke + j * 8);
        CP_COMMIT();
    };

    load_stage(0, 0);
    load_stage(1, 1);

    int s = 0;
    for (int c = 0; c < NCH; ++c) {
        if (c + 1 < NCH) { CP_WAIT(1); } else { CP_WAIT(0); }
        __syncthreads();
        if (c + 2 < NCH) load_stage(c + 2, (c + 2) % NSTG);

        const uint32_t Ab = sb + s * STAGE_BYTES;
        const uint32_t Bb = Ab + 8192;

#pragma unroll
        for (int k16 = 0; k16 < 4; ++k16) {
            uint32_t a[2][4], bb[2][4];
#pragma unroll
            for (int mt = 0; mt < 2; ++mt) {
                int r = warp_m + mt * 16 + a_row;
                ldsm4(a[mt], Ab + r * 128 + ((k16 * 32 + a_k16b) ^ ((r & 7) * 16)));
            }
#pragma unroll
            for (int p = 0; p < 2; ++p) {
                int n = warp_n + p * 16 + b_nr;
                ldsm4(bb[p], Bb + n * 128 + ((k16 * 32 + b_k16b) ^ ((n & 7) * 16)));
            }
#pragma unroll
            for (int mt = 0; mt < 2; ++mt)
#pragma unroll
                for (int nt = 0; nt < 4; ++nt)
                    mma_f16(acc[mt][nt], a[mt], &bb[nt >> 1][(nt & 1) * 2]);
        }
        s = (s + 1 == NSTG) ? 0 : s + 1;
    }

    float* Cp = g_part + (size_t)blockIdx.z * MM * DD;
#pragma unroll
    for (int mt = 0; mt < 2; ++mt)
#pragma unroll
        for (int nt = 0; nt < 4; ++nt) {
            int r    = m0 + warp_m + mt * 16 + (lane >> 2);
            int ccol = n0 + warp_n + nt * 8 + (lane & 3) * 2;
            *(float2*)&Cp[(size_t)r * DD + ccol] =
                make_float2(acc[mt][nt][0], acc[mt][nt][1]);
            *(float2*)&Cp[(size_t)(r + 8) * DD + ccol] =
                make_float2(acc[mt][nt][2], acc[mt][nt][3]);
        }
}

// ---------------------------------------------------------------------------
// Reduce split-K partials
// ---------------------------------------------------------------------------
__global__ void __launch_bounds__(256) reduce_kernel(float* __restrict__ out) {
    const int idx = blockIdx.x * 256 + threadIdx.x;
    const float4* p = (const float4*)g_part;
    float4 s = p[idx];
#pragma unroll
    for (int sp = 1; sp < SPLIT; ++sp) {
        float4 v = p[(size_t)sp * (MM * DD / 4) + idx];
        s.x += v.x; s.y += v.y; s.z += v.z; s.w += v.w;
    }
    ((float4*)out)[idx] = s;
}

extern "C" void kernel_launch(void* const* d_in, const int* in_sizes, int n_in,
                              void* d_out, int out_size) {
    const float* x     = (const float*)d_in[0];  // [32,64,512]
    const float* w     = (const float*)d_in[1];  // [64,512,512]
    const float* coeff = (const float*)d_in[2];  // [64,64,64]
    float* out = (float*)d_out;                  // [32,64,512]

    cudaFuncSetAttribute(gemm_kernel,       cudaFuncAttributeMaxDynamicSharedMemorySize, GEMM_SMEM);
    cudaFuncSetAttribute(stage1_mma_kernel, cudaFuncAttributeMaxDynamicSharedMemorySize, S1_SMEM);

    ctrans_kernel<<<KK, 256>>>(coeff);
    wsplit_kernel<<<dim3(KTOT / 32, DD / 32), 256>>>(w);
    stage1_mma_kernel<<<dim3(KK / 8, B_), 256, S1_SMEM>>>(x);
    gemm_kernel<<<dim3(DD / BN, MM / BM, SPLIT), 256, GEMM_SMEM>>>();
    reduce_kernel<<<(MM * DD / 4) / 256, 256>>>(out);
}